// round 16
// baseline (speedup 1.0000x reference)
#include <cuda_runtime.h>
#include <cuda_fp16.h>

#define NROWS 16384   // B*T
#define EDIM  1024
#define DDIM  64
#define BSZ   8
#define TSEQ  2048
#define QT    64      // attention q-tile rows
#define KT    64      // attention kv-tile rows
#define CKT   9       // kv tiles per chunk (576 keys)
#define NJOB  74      // jobs per batch = sum ceil((qt+1)/9), qt=0..31 -> grid 592

// Q pre-scale: 1/sqrt(64) * log2(e) -> scores in log2 domain (ex2 softmax).
#define QSCALE (0.125f * 1.4426950408889634f)

// Projected tensors, fp16. q pre-scaled by QSCALE. v stored transposed
// per batch: g_vt[b][d][t].
__device__ __align__(16) __half g_qh[NROWS * DDIM];
__device__ __align__(16) __half g_kh[NROWS * DDIM];
__device__ __align__(16) __half g_vt[BSZ * DDIM * TSEQ];

// Weights converted to fp16 once: [w][64][1024], w in {q,k,v}
__device__ __align__(16) __half g_wh[3 * DDIM * EDIM];

// Split-KV partials: [b][qt][chunk] -> unnormalized O (64x64), row m
// (log2 domain), row l
__device__ float g_part[(size_t)BSZ * 32 * 4 * 64 * 64];   // 16.8 MB
__device__ float g_pm[BSZ * 32 * 4 * 64];
__device__ float g_pl[BSZ * 32 * 4 * 64];

// ---------------------------------------------------------------------------
// helpers
// ---------------------------------------------------------------------------
__device__ __forceinline__ unsigned packh2(float lo, float hi) {
    __half2 h = __floats2half2_rn(lo, hi);
    return *reinterpret_cast<unsigned*>(&h);
}

__device__ __forceinline__ float ex2(float x) {
    float y;
    asm("ex2.approx.f32 %0, %1;" : "=f"(y) : "f"(x));
    return y;
}

__device__ __forceinline__ void mma16(float c[4],
                                      unsigned a0, unsigned a1,
                                      unsigned a2, unsigned a3,
                                      unsigned b0, unsigned b1) {
    asm volatile(
        "mma.sync.aligned.m16n8k16.row.col.f32.f16.f16.f32 "
        "{%0,%1,%2,%3},{%4,%5,%6,%7},{%8,%9},{%0,%1,%2,%3};\n"
        : "+f"(c[0]), "+f"(c[1]), "+f"(c[2]), "+f"(c[3])
        : "r"(a0), "r"(a1), "r"(a2), "r"(a3), "r"(b0), "r"(b1));
}

// ldmatrix x4: four 8x8 b16 matrices (B fragments of two adjacent n8 tiles).
__device__ __forceinline__ void ldsm4(unsigned& d0, unsigned& d1,
                                      unsigned& d2, unsigned& d3,
                                      unsigned addr) {
    asm volatile(
        "ldmatrix.sync.aligned.m8n8.x4.shared.b16 {%0,%1,%2,%3}, [%4];"
        : "=r"(d0), "=r"(d1), "=r"(d2), "=r"(d3) : "r"(addr));
}

__device__ __forceinline__ void cpa16(void* dst_smem, const void* src) {
    unsigned d = (unsigned)__cvta_generic_to_shared(dst_smem);
    asm volatile("cp.async.cg.shared.global [%0], [%1], 16;\n"
                 :: "r"(d), "l"(src));
}
__device__ __forceinline__ void cpa_commit() {
    asm volatile("cp.async.commit_group;\n" ::: "memory");
}
template <int N>
__device__ __forceinline__ void cpa_wait() {
    asm volatile("cp.async.wait_group %0;\n" :: "n"(N) : "memory");
}

// ---------------------------------------------------------------------------
// Weight conversion: fp32 -> fp16, once.
// ---------------------------------------------------------------------------
__global__ __launch_bounds__(256) void conv_w(
    const float* __restrict__ Wq,
    const float* __restrict__ Wk,
    const float* __restrict__ Wv)
{
    int idx = blockIdx.x * blockDim.x + threadIdx.x;   // float2 index
    int w   = idx >> 15;                               // / 32768
    int rem = idx & 32767;
    const float* W = (w == 0) ? Wq : (w == 1) ? Wk : Wv;
    float2 v = *(const float2*)&W[rem * 2];
    __half2 h = __floats2half2_rn(v.x, v.y);
    *(unsigned*)&g_wh[(size_t)w * DDIM * EDIM + rem * 2] = *(unsigned*)&h;
}

// ---------------------------------------------------------------------------
// Merged projection GEMM: 128-row slab, 256 thr, 4m x 2n, K-chunk 64,
// fp16 W, ldmatrix B-fragments, 3-stage cp.async with ONE barrier/chunk.
// Stage = 128x68 f32 (x) + 3x64x72 f16 (W) = 62464 B; 3 stages = 187392 B.
// ---------------------------------------------------------------------------
#define PROJ_XS_F    (128 * 68)                           // floats
#define PROJ_WS_H    (3 * 64 * 72)                        // halves
#define PROJ_STAGE_B (PROJ_XS_F * 4 + PROJ_WS_H * 2)      // 62464 bytes
#define PROJ_SMEM    (3 * PROJ_STAGE_B)                   // 187392

__global__ __launch_bounds__(256, 1) void proj_mma(
    const float* __restrict__ x)
{
    extern __shared__ char dynb[];

    const int tid  = threadIdx.x;
    const int lane = tid & 31;
    const int wid  = tid >> 5;
    const int wm   = wid & 3;       // 4 m-warps (32 rows each)
    const int wn   = wid >> 2;      // 2 n-warps (32 cols each)
    const int r    = lane >> 2;
    const int cq   = lane & 3;
    const int m0   = blockIdx.x * 128;

    const int roff = (lane & 7) + ((lane >> 4) << 3);
    const int coff = ((lane >> 3) & 1) << 3;

    auto prefetch = [&](int kc, int s) {
        char* stage = dynb + (size_t)s * PROJ_STAGE_B;
        float  (*xs)[68]     = (float(*)[68])stage;
        __half (*ws)[64][72] = (__half(*)[64][72])(stage + PROJ_XS_F * 4);
        int k0 = kc * 64;
#pragma unroll
        for (int i = 0; i < 8; i++) {
            int slot = tid + i * 256;        // 2048 chunks (128 rows x 16)
            int m = slot >> 4, j = slot & 15;
            cpa16(&xs[m][4 * j], &x[(size_t)(m0 + m) * EDIM + k0 + 4 * j]);
        }
#pragma unroll
        for (int i = 0; i < 6; i++) {
            int slot = tid + i * 256;        // 1536 chunks (3x64 rows x 8)
            int w = slot >> 9, rem = slot & 511;
            int d = rem >> 3, j = rem & 7;
            cpa16(&ws[w][d][8 * j],
                  &g_wh[(size_t)w * DDIM * EDIM + (size_t)d * EDIM + k0 + 8 * j]);
        }
        cpa_commit();
    };

    float acc[3][2][4][4] = {};   // [output][mt][nt][reg]

    prefetch(0, 0);
    prefetch(1, 1);
    for (int kc = 0; kc < 16; kc++) {
        const int s = kc % 3;
        if (kc < 15) cpa_wait<1>();    // chunk kc arrived (kc+1 outstanding)
        else         cpa_wait<0>();
        __syncthreads();               // all warps done consuming slot (kc-1)%3
        if (kc + 2 < 16) prefetch(kc + 2, (kc + 2) % 3);

        char* stage = dynb + (size_t)s * PROJ_STAGE_B;
        float  (*xs)[68]     = (float(*)[68])stage;
        __half (*ws)[64][72] = (__half(*)[64][72])(stage + PROJ_XS_F * 4);
        unsigned ws_lane = (unsigned)__cvta_generic_to_shared(
            &ws[0][wn * 32 + roff][coff]);

#pragma unroll
        for (int ks = 0; ks < 4; ks++) {
            int k = ks * 16;
            unsigned a[2][4];
#pragma unroll
            for (int mt = 0; mt < 2; mt++) {
                int rb = wm * 32 + mt * 16;
                float2 x0 = *(float2*)&xs[rb + r][k + 2 * cq];
                float2 x1 = *(float2*)&xs[rb + r + 8][k + 2 * cq];
                float2 x2 = *(float2*)&xs[rb + r][k + 2 * cq + 8];
                float2 x3 = *(float2*)&xs[rb + r + 8][k + 2 * cq + 8];
                a[mt][0] = packh2(x0.x, x0.y);
                a[mt][1] = packh2(x1.x, x1.y);
                a[mt][2] = packh2(x2.x, x2.y);
                a[mt][3] = packh2(x3.x, x3.y);
            }
#pragma unroll
            for (int w = 0; w < 3; w++) {
#pragma unroll
                for (int p = 0; p < 2; p++) {
                    unsigned b0e, b1e, b0o, b1o;
                    ldsm4(b0e, b1e, b0o, b1o,
                          ws_lane + (unsigned)((w * 64 + p * 16) * 72 + k) * 2u);
                    mma16(acc[w][0][2 * p],     a[0][0], a[0][1], a[0][2], a[0][3], b0e, b1e);
                    mma16(acc[w][1][2 * p],     a[1][0], a[1][1], a[1][2], a[1][3], b0e, b1e);
                    mma16(acc[w][0][2 * p + 1], a[0][0], a[0][1], a[0][2], a[0][3], b0o, b1o);
                    mma16(acc[w][1][2 * p + 1], a[1][0], a[1][1], a[1][2], a[1][3], b0o, b1o);
                }
            }
        }
    }

    // epilogue: q scaled by QSCALE (log2 domain), k natural; v transposed
#pragma unroll
    for (int mt = 0; mt < 2; mt++)
#pragma unroll
        for (int nt = 0; nt < 4; nt++) {
            int row = m0 + wm * 32 + mt * 16 + r;
            int col = wn * 32 + nt * 8 + 2 * cq;
            {
                float* a = acc[0][mt][nt];
                *(__half2*)&g_qh[(size_t)row * DDIM + col] =
                    __floats2half2_rn(a[0] * QSCALE, a[1] * QSCALE);
                *(__half2*)&g_qh[(size_t)(row + 8) * DDIM + col] =
                    __floats2half2_rn(a[2] * QSCALE, a[3] * QSCALE);
            }
            {
                float* a = acc[1][mt][nt];
                *(__half2*)&g_kh[(size_t)row * DDIM + col] =
                    __floats2half2_rn(a[0], a[1]);
                *(__half2*)&g_kh[(size_t)(row + 8) * DDIM + col] =
                    __floats2half2_rn(a[2], a[3]);
            }
            {
                float* a = acc[2][mt][nt];
                int bb = row >> 11;
                int tt = row & 2047;
                size_t vb = (size_t)bb * DDIM * TSEQ;
                g_vt[vb + (size_t)col * TSEQ + tt]           = __float2half_rn(a[0]);
                g_vt[vb + (size_t)(col + 1) * TSEQ + tt]     = __float2half_rn(a[1]);
                g_vt[vb + (size_t)col * TSEQ + tt + 8]       = __float2half_rn(a[2]);
                g_vt[vb + (size_t)(col + 1) * TSEQ + tt + 8] = __float2half_rn(a[3]);
            }
        }
}

// ---------------------------------------------------------------------------
// Split-KV flash attention (ex2 softmax). Job = (batch, q-tile, kv-chunk
// of <=9 KT-tiles). 74 jobs/batch -> 592 blocks = exactly one wave.
// ---------------------------------------------------------------------------
__global__ __launch_bounds__(128, 4) void attn_split(float* __restrict__ out)
{
    __shared__ __align__(16) __half Ks[2][KT][72];
    __shared__ __align__(16) __half Vt[2][DDIM][72];

    const int tid  = threadIdx.x;
    const int lane = tid & 31;
    const int w    = tid >> 5;
    const int r    = lane >> 2;
    const int cq   = lane & 3;
    const int b    = blockIdx.y;

    const int roff = (lane & 7) + ((lane >> 4) << 3);
    const int coff = ((lane >> 3) & 1) << 3;

    // job decode for CKT=9 (reversed so long chunks launch first)
    const int j = NJOB - 1 - blockIdx.x;
    int qt, ck;
    if (j < 9)       { qt = j;                    ck = 0; }
    else if (j < 27) { qt = 9  + (j - 9)  / 2;    ck = (j - 9)  % 2; }
    else if (j < 54) { qt = 18 + (j - 27) / 3;    ck = (j - 27) % 3; }
    else             { qt = 27 + (j - 54) / 4;    ck = (j - 54) % 4; }
    const int nch  = qt / CKT + 1;
    const int kbeg = ck * CKT;
    const int kend = min(kbeg + CKT, qt + 1);

    const int q0 = qt * QT;
    const size_t base  = (size_t)b * TSEQ * DDIM;
    const size_t vbase = (size_t)b * DDIM * TSEQ;

    auto prefetch = [&](int kt, int s) {
        int k0 = kt * KT;
#pragma unroll
        for (int i = 0; i < 4; i++) {
            int slot = tid + i * 128;
            int m = slot >> 3, jj = slot & 7;
            cpa16(&Ks[s][m][8 * jj], &g_kh[base + (size_t)(k0 + m) * DDIM + 8 * jj]);
            cpa16(&Vt[s][m][8 * jj], &g_vt[vbase + (size_t)m * TSEQ + k0 + 8 * jj]);
        }
        cpa_commit();
    };

    // Q fragments (fp16, pre-scaled to log2 domain)
    unsigned qa[4][4];
    {
        const __half* q0p = &g_qh[base + (size_t)(q0 + 16 * w + r) * DDIM];
        const __half* q1p = q0p + 8 * DDIM;
#pragma unroll
        for (int kc = 0; kc < 4; kc++) {
            int c = 16 * kc + 2 * cq;
            qa[kc][0] = *(const unsigned*)&q0p[c];
            qa[kc][1] = *(const unsigned*)&q1p[c];
            qa[kc][2] = *(const unsigned*)&q0p[c + 8];
            qa[kc][3] = *(const unsigned*)&q1p[c + 8];
        }
    }

    const unsigned ks_lane0 = (unsigned)__cvta_generic_to_shared(&Ks[0][roff][coff]);
    const unsigned vt_lane0 = (unsigned)__cvta_generic_to_shared(&Vt[0][roff][coff]);
    const unsigned stageK = (unsigned)(KT * 72 * 2);
    const unsigned stageV = (unsigned)(DDIM * 72 * 2);

    float O[8][4] = {};
    float mA = -1e30f, mB = -1e30f, lA = 0.f, lB = 0.f;

    prefetch(kbeg, 0);

    for (int kt = kbeg; kt < kend; kt++) {
        const int s  = (kt - kbeg) & 1;
        const int k0 = kt * KT;
        __syncthreads();
        if (kt + 1 < kend) { prefetch(kt + 1, s ^ 1); cpa_wait<1>(); }
        else               { cpa_wait<0>(); }
        __syncthreads();

        const unsigned ks_lane = ks_lane0 + s * stageK;
        const unsigned vt_lane = vt_lane0 + s * stageV;

        // ---- S = Q * K^T (log2-domain scores) ----
        float sacc[8][4] = {};
#pragma unroll
        for (int kc = 0; kc < 4; kc++) {
#pragma unroll
            for (int p = 0; p < 4; p++) {
                unsigned b0e, b1e, b0o, b1o;
                ldsm4(b0e, b1e, b0o, b1o,
                      ks_lane + (unsigned)((p * 16) * 72 + kc * 16) * 2u);
                mma16(sacc[2 * p],     qa[kc][0], qa[kc][1], qa[kc][2], qa[kc][3], b0e, b1e);
                mma16(sacc[2 * p + 1], qa[kc][0], qa[kc][1], qa[kc][2], qa[kc][3], b0o, b1o);
            }
        }

        // ---- causal mask (diagonal tile only) ----
        if (kt == qt) {
            int rowg = q0 + 16 * w + r;
#pragma unroll
            for (int nt = 0; nt < 8; nt++) {
                int col = k0 + nt * 8 + 2 * cq;
                if (col     > rowg)     sacc[nt][0] = -1e30f;
                if (col + 1 > rowg)     sacc[nt][1] = -1e30f;
                if (col     > rowg + 8) sacc[nt][2] = -1e30f;
                if (col + 1 > rowg + 8) sacc[nt][3] = -1e30f;
            }
        }

        // ---- warp-local online softmax via ex2 (MUFU); P in registers ----
        unsigned phA[8], phB[8];
        {
            float pmA = -1e30f, pmB = -1e30f;
#pragma unroll
            for (int nt = 0; nt < 8; nt++) {
                pmA = fmaxf(pmA, fmaxf(sacc[nt][0], sacc[nt][1]));
                pmB = fmaxf(pmB, fmaxf(sacc[nt][2], sacc[nt][3]));
            }
            pmA = fmaxf(pmA, __shfl_xor_sync(0xffffffffu, pmA, 1));
            pmA = fmaxf(pmA, __shfl_xor_sync(0xffffffffu, pmA, 2));
            pmB = fmaxf(pmB, __shfl_xor_sync(0xffffffffu, pmB, 1));
            pmB = fmaxf(pmB, __shfl_xor_sync(0xffffffffu, pmB, 2));
            float nmA = fmaxf(mA, pmA), nmB = fmaxf(mB, pmB);
            float alA = ex2(mA - nmA), alB = ex2(mB - nmB);
            mA = nmA; mB = nmB;

            float sA = 0.f, sB = 0.f;
#pragma unroll
            for (int nt = 0; nt < 8; nt++) {
                float p0 = ex2(sacc[nt][0] - nmA);
                float p1 = ex2(sacc[nt][1] - nmA);
                float p2 = ex2(sacc[nt][2] - nmB);
                float p3 = ex2(sacc[nt][3] - nmB);
                sA += p0 + p1; sB += p2 + p3;
                phA[nt] = packh2(p0, p1);
                phB[nt] = packh2(p2, p3);
            }
            sA += __shfl_xor_sync(0xffffffffu, sA, 1);
            sA += __shfl_xor_sync(0xffffffffu, sA, 2);
            sB += __shfl_xor_sync(0xffffffffu, sB, 1);
            sB += __shfl_xor_sync(0xffffffffu, sB, 2);
            lA = lA * alA + sA;
            lB = lB * alB + sB;
#pragma unroll
            for (int nt = 0; nt < 8; nt++) {
                O[nt][0] *= alA; O[nt][1] *= alA;
                O[nt][2] *= alB; O[nt][3] *= alB;
            }
        }

        // ---- O += P * V ----
#pragma unroll
        for (int kc = 0; kc < 4; kc++) {
            unsigned a0 = phA[2 * kc],     a1 = phB[2 * kc];
            unsigned a2 = phA[2 * kc + 1], a3 = phB[2 * kc + 1];
#pragma unroll
            for (int p = 0; p < 4; p++) {
                unsigned b0e, b1e, b0o, b1o;
                ldsm4(b0e, b1e, b0o, b1o,
                      vt_lane + (unsigned)((p * 16) * 72 + kc * 16) * 2u);
                mma16(O[2 * p],     a0, a1, a2, a3, b0e, b1e);
                mma16(O[2 * p + 1], a0, a1, a2, a3, b0o, b1o);
            }
        }
    }

    // ---- epilogue ----
    if (nch == 1) {
        float ilA = 1.f / lA, ilB = 1.f / lB;
        int rowg = q0 + 16 * w + r;
#pragma unroll
        for (int nt = 0; nt < 8; nt++) {
            int col = nt * 8 + 2 * cq;
            *(float2*)&out[base + (size_t)rowg * DDIM + col] =
                make_float2(O[nt][0] * ilA, O[nt][1] * ilA);
            *(float2*)&out[base + (size_t)(rowg + 8) * DDIM + col] =
                make_float2(O[nt][2] * ilB, O[nt][3] * ilB);
        }
    } else {
        const size_t slot = ((size_t)b * 32 + qt) * 4 + ck;
        float* P = g_part + slot * (64 * 64);
        int rowL = 16 * w + r;
#pragma unroll
        for (int nt = 0; nt < 8; nt++) {
            int col = nt * 8 + 2 * cq;
            *(float2*)&P[(size_t)rowL * 64 + col]       = make_float2(O[nt][0], O[nt][1]);
            *(float2*)&P[(size_t)(rowL + 8) * 64 + col] = make_float2(O[nt][2], O[nt][3]);
        }
        if (cq == 0) {
            g_pm[slot * 64 + rowL]     = mA;     // log2 domain
            g_pl[slot * 64 + rowL]     = lA;
            g_pm[slot * 64 + rowL + 8] = mB;
            g_pl[slot * 64 + rowL + 8] = lB;
        }
    }
}

// ---------------------------------------------------------------------------
// Merge kernel: combine 2..4 KV-chunk partials for q-tiles qt >= 9.
// m values are log2-domain -> ex2 weights. Grid (23, 8, 2), 256 threads.
// ---------------------------------------------------------------------------
__global__ __launch_bounds__(256) void attn_merge(float* __restrict__ out)
{
    const int qt  = 9 + blockIdx.x;
    const int b   = blockIdx.y;
    const int nch = qt / CKT + 1;
    const int tid = threadIdx.x;
    const int row = blockIdx.z * 32 + (tid >> 3);
    const int cg  = (tid & 7) * 8;

    const size_t slot0 = ((size_t)b * 32 + qt) * 4;

    float m[4], l[4];
    float M = -1e30f;
#pragma unroll
    for (int c = 0; c < 4; c++) {
        if (c < nch) {
            m[c] = g_pm[(slot0 + c) * 64 + row];
            l[c] = g_pl[(slot0 + c) * 64 + row];
            M = fmaxf(M, m[c]);
        }
    }
    float L = 0.f, sc[4];
#pragma unroll
    for (int c = 0; c < 4; c++) {
        if (c < nch) {
            sc[c] = ex2(m[c] - M);
            L += sc[c] * l[c];
        }
    }

    float4 acc[2] = {};
#pragma unroll
    for (int c = 0; c < 4; c++) {
        if (c < nch) {
            const float* P = g_part + (slot0 + c) * (64 * 64) + (size_t)row * 64 + cg;
            float wgt = sc[c];
#pragma unroll
            for (int i = 0; i < 2; i++) {
                float4 v = *(const float4*)&P[4 * i];
                acc[i].x = fmaf(wgt, v.x, acc[i].x);
                acc[i].y = fmaf(wgt, v.y, acc[i].y);
                acc[i].z = fmaf(wgt, v.z, acc[i].z);
                acc[i].w = fmaf(wgt, v.w, acc[i].w);
            }
        }
    }

    float invL = 1.f / L;
    size_t o = ((size_t)b * TSEQ + qt * QT + row) * DDIM + cg;
#pragma unroll
    for (int i = 0; i < 2; i++) {
        *(float4*)&out[o + 4 * i] = make_float4(acc[i].x * invL, acc[i].y * invL,
                                                acc[i].z * invL, acc[i].w * invL);
    }
}

// ---------------------------------------------------------------------------
// Launch
// ---------------------------------------------------------------------------
extern "C" void kernel_launch(void* const* d_in, const int* in_sizes, int n_in,
                              void* d_out, int out_size)
{
    const float* x  = (const float*)d_in[0];
    const float* Wk = (const float*)d_in[1];
    const float* Wq = (const float*)d_in[2];
    const float* Wv = (const float*)d_in[3];
    float* out = (float*)d_out;

    cudaFuncSetAttribute(proj_mma,
                         cudaFuncAttributeMaxDynamicSharedMemorySize, PROJ_SMEM);

    conv_w<<<384, 256>>>(Wq, Wk, Wv);
    proj_mma<<<NROWS / 128, 256, PROJ_SMEM>>>(x);
    attn_split<<<dim3(NJOB, BSZ), 128>>>(out);
    attn_merge<<<dim3(23, BSZ, 2), 256>>>(out);
}

// round 17
// speedup vs baseline: 1.0274x; 1.0274x over previous
#include <cuda_runtime.h>
#include <cuda_fp16.h>

#define NROWS 16384   // B*T
#define EDIM  1024
#define DDIM  64
#define BSZ   8
#define TSEQ  2048
#define QT    64      // attention q-tile rows
#define KT    64      // attention kv-tile rows
#define CKT   8       // kv tiles per chunk (512 keys)
#define NJOB  80      // jobs per batch = sum ceil((qt+1)/8), qt=0..31

// Q pre-scale: 1/sqrt(64) * log2(e) -> scores in log2 domain (ex2 softmax).
#define QSCALE (0.125f * 1.4426950408889634f)

// Projected tensors, fp16. q pre-scaled by QSCALE. v stored transposed
// per batch: g_vt[b][d][t].
__device__ __align__(16) __half g_qh[NROWS * DDIM];
__device__ __align__(16) __half g_kh[NROWS * DDIM];
__device__ __align__(16) __half g_vt[BSZ * DDIM * TSEQ];

// Weights converted to fp16 once: [w][64][1024], w in {q,k,v}
__device__ __align__(16) __half g_wh[3 * DDIM * EDIM];

// Split-KV partials: [b][qt][chunk] -> unnormalized O (64x64), row m
// (log2 domain), row l. Only ever holds finite values (zero-init or
// written partials), so unconditional reads are safe.
__device__ float g_part[(size_t)BSZ * 32 * 4 * 64 * 64];   // 16.8 MB
__device__ float g_pm[BSZ * 32 * 4 * 64];
__device__ float g_pl[BSZ * 32 * 4 * 64];

// ---------------------------------------------------------------------------
// helpers
// ---------------------------------------------------------------------------
__device__ __forceinline__ unsigned packh2(float lo, float hi) {
    __half2 h = __floats2half2_rn(lo, hi);
    return *reinterpret_cast<unsigned*>(&h);
}

__device__ __forceinline__ float ex2(float x) {
    float y;
    asm("ex2.approx.f32 %0, %1;" : "=f"(y) : "f"(x));
    return y;
}

__device__ __forceinline__ void mma16(float c[4],
                                      unsigned a0, unsigned a1,
                                      unsigned a2, unsigned a3,
                                      unsigned b0, unsigned b1) {
    asm volatile(
        "mma.sync.aligned.m16n8k16.row.col.f32.f16.f16.f32 "
        "{%0,%1,%2,%3},{%4,%5,%6,%7},{%8,%9},{%0,%1,%2,%3};\n"
        : "+f"(c[0]), "+f"(c[1]), "+f"(c[2]), "+f"(c[3])
        : "r"(a0), "r"(a1), "r"(a2), "r"(a3), "r"(b0), "r"(b1));
}

// ldmatrix x4: four 8x8 b16 matrices (B fragments of two adjacent n8 tiles).
__device__ __forceinline__ void ldsm4(unsigned& d0, unsigned& d1,
                                      unsigned& d2, unsigned& d3,
                                      unsigned addr) {
    asm volatile(
        "ldmatrix.sync.aligned.m8n8.x4.shared.b16 {%0,%1,%2,%3}, [%4];"
        : "=r"(d0), "=r"(d1), "=r"(d2), "=r"(d3) : "r"(addr));
}

__device__ __forceinline__ void cpa16(void* dst_smem, const void* src) {
    unsigned d = (unsigned)__cvta_generic_to_shared(dst_smem);
    asm volatile("cp.async.cg.shared.global [%0], [%1], 16;\n"
                 :: "r"(d), "l"(src));
}
__device__ __forceinline__ void cpa_commit() {
    asm volatile("cp.async.commit_group;\n" ::: "memory");
}
template <int N>
__device__ __forceinline__ void cpa_wait() {
    asm volatile("cp.async.wait_group %0;\n" :: "n"(N) : "memory");
}

// ---------------------------------------------------------------------------
// Weight conversion: fp32 -> fp16, once.
// ---------------------------------------------------------------------------
__global__ __launch_bounds__(256) void conv_w(
    const float* __restrict__ Wq,
    const float* __restrict__ Wk,
    const float* __restrict__ Wv)
{
    int idx = blockIdx.x * blockDim.x + threadIdx.x;   // float2 index
    int w   = idx >> 15;                               // / 32768
    int rem = idx & 32767;
    const float* W = (w == 0) ? Wq : (w == 1) ? Wk : Wv;
    float2 v = *(const float2*)&W[rem * 2];
    __half2 h = __floats2half2_rn(v.x, v.y);
    *(unsigned*)&g_wh[(size_t)w * DDIM * EDIM + rem * 2] = *(unsigned*)&h;
}

// ---------------------------------------------------------------------------
// Merged projection GEMM (R15-committed config).
// 128-row slab, 256 thr, 4m x 2n, K-chunk 64, 2-stage cp.async, fp16 W,
// ldmatrix B-fragments.
// ---------------------------------------------------------------------------
#define PROJ_XS_F    (128 * 68)                           // floats
#define PROJ_WS_H    (3 * 64 * 72)                        // halves
#define PROJ_STAGE_B (PROJ_XS_F * 4 + PROJ_WS_H * 2)      // 62464 bytes
#define PROJ_SMEM    (2 * PROJ_STAGE_B)                   // 124928

__global__ __launch_bounds__(256, 1) void proj_mma(
    const float* __restrict__ x)
{
    extern __shared__ char dynb[];

    const int tid  = threadIdx.x;
    const int lane = tid & 31;
    const int wid  = tid >> 5;
    const int wm   = wid & 3;       // 4 m-warps (32 rows each)
    const int wn   = wid >> 2;      // 2 n-warps (32 cols each)
    const int r    = lane >> 2;
    const int cq   = lane & 3;
    const int m0   = blockIdx.x * 128;

    const int roff = (lane & 7) + ((lane >> 4) << 3);
    const int coff = ((lane >> 3) & 1) << 3;

    auto prefetch = [&](int kc, int s) {
        char* stage = dynb + (size_t)s * PROJ_STAGE_B;
        float  (*xs)[68]     = (float(*)[68])stage;
        __half (*ws)[64][72] = (__half(*)[64][72])(stage + PROJ_XS_F * 4);
        int k0 = kc * 64;
#pragma unroll
        for (int i = 0; i < 8; i++) {
            int slot = tid + i * 256;        // 2048 chunks (128 rows x 16)
            int m = slot >> 4, j = slot & 15;
            cpa16(&xs[m][4 * j], &x[(size_t)(m0 + m) * EDIM + k0 + 4 * j]);
        }
#pragma unroll
        for (int i = 0; i < 6; i++) {
            int slot = tid + i * 256;        // 1536 chunks (3x64 rows x 8)
            int w = slot >> 9, rem = slot & 511;
            int d = rem >> 3, j = rem & 7;
            cpa16(&ws[w][d][8 * j],
                  &g_wh[(size_t)w * DDIM * EDIM + (size_t)d * EDIM + k0 + 8 * j]);
        }
        cpa_commit();
    };

    float acc[3][2][4][4] = {};   // [output][mt][nt][reg]

    prefetch(0, 0);
    for (int kc = 0; kc < 16; kc++) {
        const int s = kc & 1;
        __syncthreads();
        if (kc + 1 < 16) { prefetch(kc + 1, s ^ 1); cpa_wait<1>(); }
        else             { cpa_wait<0>(); }
        __syncthreads();

        char* stage = dynb + (size_t)s * PROJ_STAGE_B;
        float  (*xs)[68]     = (float(*)[68])stage;
        __half (*ws)[64][72] = (__half(*)[64][72])(stage + PROJ_XS_F * 4);
        unsigned ws_lane = (unsigned)__cvta_generic_to_shared(
            &ws[0][wn * 32 + roff][coff]);

#pragma unroll
        for (int ks = 0; ks < 4; ks++) {
            int k = ks * 16;
            unsigned a[2][4];
#pragma unroll
            for (int mt = 0; mt < 2; mt++) {
                int rb = wm * 32 + mt * 16;
                float2 x0 = *(float2*)&xs[rb + r][k + 2 * cq];
                float2 x1 = *(float2*)&xs[rb + r + 8][k + 2 * cq];
                float2 x2 = *(float2*)&xs[rb + r][k + 2 * cq + 8];
                float2 x3 = *(float2*)&xs[rb + r + 8][k + 2 * cq + 8];
                a[mt][0] = packh2(x0.x, x0.y);
                a[mt][1] = packh2(x1.x, x1.y);
                a[mt][2] = packh2(x2.x, x2.y);
                a[mt][3] = packh2(x3.x, x3.y);
            }
#pragma unroll
            for (int w = 0; w < 3; w++) {
#pragma unroll
                for (int p = 0; p < 2; p++) {
                    unsigned b0e, b1e, b0o, b1o;
                    ldsm4(b0e, b1e, b0o, b1o,
                          ws_lane + (unsigned)((w * 64 + p * 16) * 72 + k) * 2u);
                    mma16(acc[w][0][2 * p],     a[0][0], a[0][1], a[0][2], a[0][3], b0e, b1e);
                    mma16(acc[w][1][2 * p],     a[1][0], a[1][1], a[1][2], a[1][3], b0e, b1e);
                    mma16(acc[w][0][2 * p + 1], a[0][0], a[0][1], a[0][2], a[0][3], b0o, b1o);
                    mma16(acc[w][1][2 * p + 1], a[1][0], a[1][1], a[1][2], a[1][3], b0o, b1o);
                }
            }
        }
    }

    // epilogue: q scaled by QSCALE (log2 domain), k natural; v transposed
#pragma unroll
    for (int mt = 0; mt < 2; mt++)
#pragma unroll
        for (int nt = 0; nt < 4; nt++) {
            int row = m0 + wm * 32 + mt * 16 + r;
            int col = wn * 32 + nt * 8 + 2 * cq;
            {
                float* a = acc[0][mt][nt];
                *(__half2*)&g_qh[(size_t)row * DDIM + col] =
                    __floats2half2_rn(a[0] * QSCALE, a[1] * QSCALE);
                *(__half2*)&g_qh[(size_t)(row + 8) * DDIM + col] =
                    __floats2half2_rn(a[2] * QSCALE, a[3] * QSCALE);
            }
            {
                float* a = acc[1][mt][nt];
                *(__half2*)&g_kh[(size_t)row * DDIM + col] =
                    __floats2half2_rn(a[0], a[1]);
                *(__half2*)&g_kh[(size_t)(row + 8) * DDIM + col] =
                    __floats2half2_rn(a[2], a[3]);
            }
            {
                float* a = acc[2][mt][nt];
                int bb = row >> 11;
                int tt = row & 2047;
                size_t vb = (size_t)bb * DDIM * TSEQ;
                g_vt[vb + (size_t)col * TSEQ + tt]           = __float2half_rn(a[0]);
                g_vt[vb + (size_t)(col + 1) * TSEQ + tt]     = __float2half_rn(a[1]);
                g_vt[vb + (size_t)col * TSEQ + tt + 8]       = __float2half_rn(a[2]);
                g_vt[vb + (size_t)(col + 1) * TSEQ + tt + 8] = __float2half_rn(a[3]);
            }
        }
}

// ---------------------------------------------------------------------------
// Split-KV flash attention (R15 loop; ex2 softmax, log2 domain).
// Job = (batch, q-tile, kv-chunk of <=8 KT-tiles). 640 blocks.
// ---------------------------------------------------------------------------
__global__ __launch_bounds__(128, 4) void attn_split(float* __restrict__ out)
{
    __shared__ __align__(16) __half Ks[2][KT][72];
    __shared__ __align__(16) __half Vt[2][DDIM][72];

    const int tid  = threadIdx.x;
    const int lane = tid & 31;
    const int w    = tid >> 5;
    const int r    = lane >> 2;
    const int cq   = lane & 3;
    const int b    = blockIdx.y;

    const int roff = (lane & 7) + ((lane >> 4) << 3);
    const int coff = ((lane >> 3) & 1) << 3;

    // job decode (reversed so 8-tile chunks launch first)
    const int j = NJOB - 1 - blockIdx.x;
    int qt, ck;
    if (j < 8)       { qt = j;                   ck = 0; }
    else if (j < 24) { qt = 8  + ((j - 8)  >> 1); ck = (j - 8)  & 1; }
    else if (j < 48) { qt = 16 + (j - 24) / 3;    ck = (j - 24) % 3; }
    else             { qt = 24 + ((j - 48) >> 2); ck = (j - 48) & 3; }
    const int nch  = qt / CKT + 1;
    const int kbeg = ck * CKT;
    const int kend = min(kbeg + CKT, qt + 1);

    const int q0 = qt * QT;
    const size_t base  = (size_t)b * TSEQ * DDIM;
    const size_t vbase = (size_t)b * DDIM * TSEQ;

    auto prefetch = [&](int kt, int s) {
        int k0 = kt * KT;
#pragma unroll
        for (int i = 0; i < 4; i++) {
            int slot = tid + i * 128;
            int m = slot >> 3, jj = slot & 7;
            cpa16(&Ks[s][m][8 * jj], &g_kh[base + (size_t)(k0 + m) * DDIM + 8 * jj]);
            cpa16(&Vt[s][m][8 * jj], &g_vt[vbase + (size_t)m * TSEQ + k0 + 8 * jj]);
        }
        cpa_commit();
    };

    // Q fragments (fp16, pre-scaled to log2 domain)
    unsigned qa[4][4];
    {
        const __half* q0p = &g_qh[base + (size_t)(q0 + 16 * w + r) * DDIM];
        const __half* q1p = q0p + 8 * DDIM;
#pragma unroll
        for (int kc = 0; kc < 4; kc++) {
            int c = 16 * kc + 2 * cq;
            qa[kc][0] = *(const unsigned*)&q0p[c];
            qa[kc][1] = *(const unsigned*)&q1p[c];
            qa[kc][2] = *(const unsigned*)&q0p[c + 8];
            qa[kc][3] = *(const unsigned*)&q1p[c + 8];
        }
    }

    const unsigned ks_lane0 = (unsigned)__cvta_generic_to_shared(&Ks[0][roff][coff]);
    const unsigned vt_lane0 = (unsigned)__cvta_generic_to_shared(&Vt[0][roff][coff]);
    const unsigned stageK = (unsigned)(KT * 72 * 2);
    const unsigned stageV = (unsigned)(DDIM * 72 * 2);

    float O[8][4] = {};
    float mA = -1e30f, mB = -1e30f, lA = 0.f, lB = 0.f;

    prefetch(kbeg, 0);

    for (int kt = kbeg; kt < kend; kt++) {
        const int s  = (kt - kbeg) & 1;
        const int k0 = kt * KT;
        __syncthreads();
        if (kt + 1 < kend) { prefetch(kt + 1, s ^ 1); cpa_wait<1>(); }
        else               { cpa_wait<0>(); }
        __syncthreads();

        const unsigned ks_lane = ks_lane0 + s * stageK;
        const unsigned vt_lane = vt_lane0 + s * stageV;

        // ---- S = Q * K^T (log2-domain scores) ----
        float sacc[8][4] = {};
#pragma unroll
        for (int kc = 0; kc < 4; kc++) {
#pragma unroll
            for (int p = 0; p < 4; p++) {
                unsigned b0e, b1e, b0o, b1o;
                ldsm4(b0e, b1e, b0o, b1o,
                      ks_lane + (unsigned)((p * 16) * 72 + kc * 16) * 2u);
                mma16(sacc[2 * p],     qa[kc][0], qa[kc][1], qa[kc][2], qa[kc][3], b0e, b1e);
                mma16(sacc[2 * p + 1], qa[kc][0], qa[kc][1], qa[kc][2], qa[kc][3], b0o, b1o);
            }
        }

        // ---- causal mask (diagonal tile only) ----
        if (kt == qt) {
            int rowg = q0 + 16 * w + r;
#pragma unroll
            for (int nt = 0; nt < 8; nt++) {
                int col = k0 + nt * 8 + 2 * cq;
                if (col     > rowg)     sacc[nt][0] = -1e30f;
                if (col + 1 > rowg)     sacc[nt][1] = -1e30f;
                if (col     > rowg + 8) sacc[nt][2] = -1e30f;
                if (col + 1 > rowg + 8) sacc[nt][3] = -1e30f;
            }
        }

        // ---- warp-local online softmax via ex2 (MUFU); P in registers ----
        unsigned phA[8], phB[8];
        {
            float pmA = -1e30f, pmB = -1e30f;
#pragma unroll
            for (int nt = 0; nt < 8; nt++) {
                pmA = fmaxf(pmA, fmaxf(sacc[nt][0], sacc[nt][1]));
                pmB = fmaxf(pmB, fmaxf(sacc[nt][2], sacc[nt][3]));
            }
            pmA = fmaxf(pmA, __shfl_xor_sync(0xffffffffu, pmA, 1));
            pmA = fmaxf(pmA, __shfl_xor_sync(0xffffffffu, pmA, 2));
            pmB = fmaxf(pmB, __shfl_xor_sync(0xffffffffu, pmB, 1));
            pmB = fmaxf(pmB, __shfl_xor_sync(0xffffffffu, pmB, 2));
            float nmA = fmaxf(mA, pmA), nmB = fmaxf(mB, pmB);
            float alA = ex2(mA - nmA), alB = ex2(mB - nmB);
            mA = nmA; mB = nmB;

            float sA = 0.f, sB = 0.f;
#pragma unroll
            for (int nt = 0; nt < 8; nt++) {
                float p0 = ex2(sacc[nt][0] - nmA);
                float p1 = ex2(sacc[nt][1] - nmA);
                float p2 = ex2(sacc[nt][2] - nmB);
                float p3 = ex2(sacc[nt][3] - nmB);
                sA += p0 + p1; sB += p2 + p3;
                phA[nt] = packh2(p0, p1);
                phB[nt] = packh2(p2, p3);
            }
            sA += __shfl_xor_sync(0xffffffffu, sA, 1);
            sA += __shfl_xor_sync(0xffffffffu, sA, 2);
            sB += __shfl_xor_sync(0xffffffffu, sB, 1);
            sB += __shfl_xor_sync(0xffffffffu, sB, 2);
            lA = lA * alA + sA;
            lB = lB * alB + sB;
#pragma unroll
            for (int nt = 0; nt < 8; nt++) {
                O[nt][0] *= alA; O[nt][1] *= alA;
                O[nt][2] *= alB; O[nt][3] *= alB;
            }
        }

        // ---- O += P * V ----
#pragma unroll
        for (int kc = 0; kc < 4; kc++) {
            unsigned a0 = phA[2 * kc],     a1 = phB[2 * kc];
            unsigned a2 = phA[2 * kc + 1], a3 = phB[2 * kc + 1];
#pragma unroll
            for (int p = 0; p < 4; p++) {
                unsigned b0e, b1e, b0o, b1o;
                ldsm4(b0e, b1e, b0o, b1o,
                      vt_lane + (unsigned)((p * 16) * 72 + kc * 16) * 2u);
                mma16(O[2 * p],     a0, a1, a2, a3, b0e, b1e);
                mma16(O[2 * p + 1], a0, a1, a2, a3, b0o, b1o);
            }
        }
    }

    // ---- epilogue ----
    if (nch == 1) {
        float ilA = 1.f / lA, ilB = 1.f / lB;
        int rowg = q0 + 16 * w + r;
#pragma unroll
        for (int nt = 0; nt < 8; nt++) {
            int col = nt * 8 + 2 * cq;
            *(float2*)&out[base + (size_t)rowg * DDIM + col] =
                make_float2(O[nt][0] * ilA, O[nt][1] * ilA);
            *(float2*)&out[base + (size_t)(rowg + 8) * DDIM + col] =
                make_float2(O[nt][2] * ilB, O[nt][3] * ilB);
        }
    } else {
        const size_t slot = ((size_t)b * 32 + qt) * 4 + ck;
        float* P = g_part + slot * (64 * 64);
        int rowL = 16 * w + r;
#pragma unroll
        for (int nt = 0; nt < 8; nt++) {
            int col = nt * 8 + 2 * cq;
            *(float2*)&P[(size_t)rowL * 64 + col]       = make_float2(O[nt][0], O[nt][1]);
            *(float2*)&P[(size_t)(rowL + 8) * 64 + col] = make_float2(O[nt][2], O[nt][3]);
        }
        if (cq == 0) {
            g_pm[slot * 64 + rowL]     = mA;     // log2 domain
            g_pl[slot * 64 + rowL]     = lA;
            g_pm[slot * 64 + rowL + 8] = mB;
            g_pl[slot * 64 + rowL + 8] = lB;
        }
    }
}

// ---------------------------------------------------------------------------
// Merge kernel: combine 2..4 KV-chunk partials for q-tiles qt >= 8.
// ALL loads unconditional (slots always hold finite values); invalid
// chunks masked with weight 0 -> 8+ independent LDGs in flight per thread.
// Grid (24, 8, 2), 256 threads.
// ---------------------------------------------------------------------------
__global__ __launch_bounds__(256) void attn_merge(float* __restrict__ out)
{
    const int qt  = 8 + blockIdx.x;
    const int b   = blockIdx.y;
    const int nch = qt / CKT + 1;
    const int tid = threadIdx.x;
    const int row = blockIdx.z * 32 + (tid >> 3);
    const int cg  = (tid & 7) * 8;

    const size_t slot0 = ((size_t)b * 32 + qt) * 4;

    // unconditional m/l loads (4 each, independent)
    float m[4], l[4];
#pragma unroll
    for (int c = 0; c < 4; c++) {
        m[c] = g_pm[(slot0 + c) * 64 + row];
        l[c] = g_pl[(slot0 + c) * 64 + row];
    }
    // unconditional partial loads: 4 chunks x 2 float4 = 8 independent LDGs
    float4 v0[4], v1[4];
#pragma unroll
    for (int c = 0; c < 4; c++) {
        const float4* P = (const float4*)(g_part + (slot0 + c) * (64 * 64)
                                          + (size_t)row * 64 + cg);
        v0[c] = P[0];
        v1[c] = P[1];
    }

    float M = -1e30f;
#pragma unroll
    for (int c = 0; c < 4; c++)
        if (c < nch) M = fmaxf(M, m[c]);

    float L = 0.f;
    float4 a0 = make_float4(0.f, 0.f, 0.f, 0.f);
    float4 a1 = make_float4(0.f, 0.f, 0.f, 0.f);
#pragma unroll
    for (int c = 0; c < 4; c++) {
        float wgt = (c < nch) ? ex2(m[c] - M) : 0.f;
        L += wgt * l[c];
        a0.x = fmaf(wgt, v0[c].x, a0.x); a0.y = fmaf(wgt, v0[c].y, a0.y);
        a0.z = fmaf(wgt, v0[c].z, a0.z); a0.w = fmaf(wgt, v0[c].w, a0.w);
        a1.x = fmaf(wgt, v1[c].x, a1.x); a1.y = fmaf(wgt, v1[c].y, a1.y);
        a1.z = fmaf(wgt, v1[c].z, a1.z); a1.w = fmaf(wgt, v1[c].w, a1.w);
    }

    float invL = 1.f / L;
    size_t o = ((size_t)b * TSEQ + qt * QT + row) * DDIM + cg;
    *(float4*)&out[o]     = make_float4(a0.x * invL, a0.y * invL,
                                        a0.z * invL, a0.w * invL);
    *(float4*)&out[o + 4] = make_float4(a1.x * invL, a1.y * invL,
                                        a1.z * invL, a1.w * invL);
}

// ---------------------------------------------------------------------------
// Launch
// ---------------------------------------------------------------------------
extern "C" void kernel_launch(void* const* d_in, const int* in_sizes, int n_in,
                              void* d_out, int out_size)
{
    const float* x  = (const float*)d_in[0];
    const float* Wk = (const float*)d_in[1];
    const float* Wq = (const float*)d_in[2];
    const float* Wv = (const float*)d_in[3];
    float* out = (float*)d_out;

    cudaFuncSetAttribute(proj_mma,
                         cudaFuncAttributeMaxDynamicSharedMemorySize, PROJ_SMEM);

    conv_w<<<384, 256>>>(Wq, Wk, Wv);
    proj_mma<<<NROWS / 128, 256, PROJ_SMEM>>>(x);
    attn_split<<<dim3(NJOB, BSZ), 128>>>(out);
    attn_merge<<<dim3(24, BSZ, 2), 256>>>(out);
}